// round 9
// baseline (speedup 1.0000x reference)
#include <cuda_runtime.h>
#include <cuda_bf16.h>
#include <cstdint>

#define B_    1024
#define N_    128
#define DIN_  256
#define HID_  256
#define DOUT_ 256
#define KDIM_ 512

#define TILE_B 16384   // one [128 rows][64 k] split-bf16 tile (swizzled)

// ---------------- scratch (static device globals; no allocation) ----------------
__device__ unsigned char g_xhi[(size_t)1024 * 4 * TILE_B];
__device__ unsigned char g_xlo[(size_t)1024 * 4 * TILE_B];
__device__ unsigned char g_whi[(size_t)12 * 4 * TILE_B];
__device__ unsigned char g_wlo[(size_t)12 * 4 * TILE_B];
__device__ unsigned char g_qhi[(size_t)1024 * 8 * TILE_B];
__device__ unsigned char g_qlo[(size_t)1024 * 8 * TILE_B];
__device__ unsigned char g_khi[(size_t)1024 * 8 * TILE_B];
__device__ unsigned char g_klo[(size_t)1024 * 8 * TILE_B];
// v^T tiles: per batch: (hb 0..1) x (tc 0..1), index = (b*2+hb)*2+tc
__device__ unsigned char g_vthi[(size_t)1024 * 4 * TILE_B];
__device__ unsigned char g_vtlo[(size_t)1024 * 4 * TILE_B];

// ================================================================================
// helpers
// ================================================================================
__device__ __forceinline__ uint32_t smem_u32(const void* p) {
    uint32_t a;
    asm("{ .reg .u64 t; cvta.to.shared.u64 t, %1; cvt.u32.u64 %0, t; }" : "=r"(a) : "l"(p));
    return a;
}
__device__ __forceinline__ void ldm_x4(uint32_t* r, uint32_t addr) {
    asm volatile("ldmatrix.sync.aligned.m8n8.x4.shared.b16 {%0,%1,%2,%3}, [%4];"
                 : "=r"(r[0]), "=r"(r[1]), "=r"(r[2]), "=r"(r[3]) : "r"(addr));
}
__device__ __forceinline__ void ldm_x2(uint32_t* r, uint32_t addr) {
    asm volatile("ldmatrix.sync.aligned.m8n8.x2.shared.b16 {%0,%1}, [%2];"
                 : "=r"(r[0]), "=r"(r[1]) : "r"(addr));
}
__device__ __forceinline__ void mma_bf16(float* c, const uint32_t* a, const uint32_t* b) {
    asm volatile(
        "mma.sync.aligned.m16n8k16.row.col.f32.bf16.bf16.f32 "
        "{%0,%1,%2,%3}, {%4,%5,%6,%7}, {%8,%9}, {%0,%1,%2,%3};"
        : "+f"(c[0]), "+f"(c[1]), "+f"(c[2]), "+f"(c[3])
        : "r"(a[0]), "r"(a[1]), "r"(a[2]), "r"(a[3]), "r"(b[0]), "r"(b[1]));
}
__device__ __forceinline__ uint32_t pack_hilo(float x, float y, uint32_t& lo_out) {
    __nv_bfloat162 h = __floats2bfloat162_rn(x, y);
    float lx = x - __low2float(h);
    float ly = y - __high2float(h);
    __nv_bfloat162 l = __floats2bfloat162_rn(lx, ly);
    lo_out = *reinterpret_cast<uint32_t*>(&l);
    return *reinterpret_cast<uint32_t*>(&h);
}
__device__ __forceinline__ uint32_t tile_off(int row, int k) {
    int g = k >> 3;
    return (uint32_t)(row * 128 + ((g ^ (row & 7)) << 4) + ((k & 7) << 1));
}

#define CP16(dst_s, src_g) \
    asm volatile("cp.async.cg.shared.global [%0], [%1], 16;" :: "r"(dst_s), "l"(src_g) : "memory")
#define CP_COMMIT() asm volatile("cp.async.commit_group;" ::: "memory")
#define CP_WAIT0()  asm volatile("cp.async.wait_group 0;" ::: "memory")

// ================================================================================
// generic MMA block over one staged 64k chunk: MF m-frags x NF n-frags, 3 passes
// ================================================================================
template<int MF, int NF>
__device__ __forceinline__ void mma_block(
    uint32_t aHi, uint32_t aLo, uint32_t bHi, uint32_t bLo,
    const uint32_t* rowA, const uint32_t* rowB,
    int gA, int gB, int l7, float (*c)[NF][4])
{
    #pragma unroll
    for (int ks = 0; ks < 4; ks++) {
        uint32_t pa = (uint32_t)((((ks << 1) + gA) ^ l7) << 4);
        uint32_t pb = (uint32_t)((((ks << 1) + gB) ^ l7) << 4);
        uint32_t a[MF][4];
        #pragma unroll
        for (int mf = 0; mf < MF; mf++) ldm_x4(a[mf], aHi + rowA[mf] + pa);
        #pragma unroll
        for (int nf = 0; nf < NF; nf++) {
            uint32_t b[2]; ldm_x2(b, bHi + rowB[nf] + pb);
            #pragma unroll
            for (int mf = 0; mf < MF; mf++) mma_bf16(c[mf][nf], a[mf], b);
        }
        #pragma unroll
        for (int nf = 0; nf < NF; nf++) {
            uint32_t b[2]; ldm_x2(b, bLo + rowB[nf] + pb);
            #pragma unroll
            for (int mf = 0; mf < MF; mf++) mma_bf16(c[mf][nf], a[mf], b);
        }
        #pragma unroll
        for (int mf = 0; mf < MF; mf++) ldm_x4(a[mf], aLo + rowA[mf] + pa);
        #pragma unroll
        for (int nf = 0; nf < NF; nf++) {
            uint32_t b[2]; ldm_x2(b, bHi + rowB[nf] + pb);
            #pragma unroll
            for (int mf = 0; mf < MF; mf++) mma_bf16(c[mf][nf], a[mf], b);
        }
    }
}

// ================================================================================
// split_x / split_w
// ================================================================================
__global__ __launch_bounds__(256) void split_x_kernel(const float* __restrict__ x)
{
    const int mt = blockIdx.x, tid = threadIdx.x;
    const float* A = x + (size_t)mt * 128 * DIN_;
    unsigned char* dh = g_xhi + (size_t)mt * 4 * TILE_B;
    unsigned char* dl = g_xlo + (size_t)mt * 4 * TILE_B;
    #pragma unroll
    for (int i = 0; i < 16; i++) {
        int G = tid + i * 256;
        int m = G >> 5, gg = G & 31;
        int ch = gg >> 3, g = gg & 7;
        const float* p = A + (size_t)m * DIN_ + gg * 8;
        float4 v0 = *(const float4*)p, v1 = *(const float4*)(p + 4);
        uint4 hi, lo;
        hi.x = pack_hilo(v0.x, v0.y, lo.x);
        hi.y = pack_hilo(v0.z, v0.w, lo.y);
        hi.z = pack_hilo(v1.x, v1.y, lo.z);
        hi.w = pack_hilo(v1.z, v1.w, lo.w);
        uint32_t off = (uint32_t)(ch * TILE_B + m * 128 + ((g ^ (m & 7)) << 4));
        *(uint4*)(dh + off) = hi;
        *(uint4*)(dl + off) = lo;
    }
}

__global__ __launch_bounds__(256) void split_w_kernel(
    const float* __restrict__ Wv, const float* __restrict__ Wq,
    const float* __restrict__ Wk, const float* __restrict__ Wo)
{
    __shared__ float wst[64 * 132];
    const int tt = blockIdx.x, tid = threadIdx.x;
    const float* W; int wld, c0;
    if (tt < 2)       { W = Wv; wld = HID_;  c0 = tt * 128; }
    else if (tt < 6)  { W = Wq; wld = KDIM_; c0 = (tt - 2) * 128; }
    else if (tt < 10) { W = Wk; wld = KDIM_; c0 = (tt - 6) * 128; }
    else              { W = Wo; wld = DOUT_; c0 = (tt - 10) * 128; }

    unsigned char* dh = g_whi + (size_t)tt * 4 * TILE_B;
    unsigned char* dl = g_wlo + (size_t)tt * 4 * TILE_B;

    for (int ch = 0; ch < 4; ch++) {
        #pragma unroll
        for (int i = 0; i < 8; i++) {
            int idx = tid + i * 256;
            int kr = idx >> 5, nq = (idx & 31) << 2;
            *(float4*)(wst + kr * 132 + nq) =
                *(const float4*)(W + (size_t)(ch * 64 + kr) * wld + c0 + nq);
        }
        __syncthreads();
        {
            int n = tid & 127, ks2 = tid >> 7;
            #pragma unroll
            for (int j = 0; j < 4; j++) {
                int g = ks2 * 4 + j, kb = g * 8;
                float v[8];
                #pragma unroll
                for (int t = 0; t < 8; t++) v[t] = wst[(kb + t) * 132 + n];
                uint4 hi, lo;
                hi.x = pack_hilo(v[0], v[1], lo.x);
                hi.y = pack_hilo(v[2], v[3], lo.y);
                hi.z = pack_hilo(v[4], v[5], lo.z);
                hi.w = pack_hilo(v[6], v[7], lo.w);
                uint32_t off = (uint32_t)(ch * TILE_B + n * 128 + ((g ^ (n & 7)) << 4));
                *(uint4*)(dh + off) = hi;
                *(uint4*)(dl + off) = lo;
            }
        }
        __syncthreads();
    }
}

// ================================================================================
// qkv: grid (10, 1024), 256 threads, 64KB smem, 2 CTA/SM (unchanged, proven).
// ================================================================================
__global__ __launch_bounds__(256, 2) void qkv_tc(
    const float* __restrict__ bv, const float* __restrict__ bq, const float* __restrict__ bk)
{
    extern __shared__ char sm[];
    const int nt = blockIdx.x, mt = blockIdx.y;
    const int tid = threadIdx.x, lane = tid & 31, wid = tid >> 5;
    const int wm = wid >> 2, wn = wid & 3;
    const int l15 = lane & 15, l7 = lane & 7;
    const int gA = lane >> 4, gB = (lane >> 3) & 1;
    const uint32_t base = smem_u32(sm);

    uint32_t rowA[4], rowB[4];
    #pragma unroll
    for (int mf = 0; mf < 4; mf++) rowA[mf] = (uint32_t)((wm * 64 + mf * 16 + l15) * 128);
    #pragma unroll
    for (int nf = 0; nf < 4; nf++) rowB[nf] = (uint32_t)((wn * 32 + nf * 8 + l7) * 128);

    float c[4][4][4];
    #pragma unroll
    for (int i = 0; i < 4; i++)
        #pragma unroll
        for (int j = 0; j < 4; j++)
            #pragma unroll
            for (int t = 0; t < 4; t++) c[i][j][t] = 0.f;

    const unsigned char* Ah = g_xhi + (size_t)mt * 4 * TILE_B;
    const unsigned char* Al = g_xlo + (size_t)mt * 4 * TILE_B;
    const unsigned char* Bh = g_whi + (size_t)nt * 4 * TILE_B;
    const unsigned char* Bl = g_wlo + (size_t)nt * 4 * TILE_B;

    for (int ch = 0; ch < 4; ch++) {
        size_t src = (size_t)ch * TILE_B;
        #pragma unroll
        for (int j = 0; j < 4; j++) {
            uint32_t o = (uint32_t)((tid + j * 256) * 16);
            CP16(base + o,         Ah + src + o);
            CP16(base + 16384 + o, Al + src + o);
            CP16(base + 32768 + o, Bh + src + o);
            CP16(base + 49152 + o, Bl + src + o);
        }
        CP_COMMIT();
        CP_WAIT0();
        __syncthreads();
        mma_block<4, 4>(base, base + 16384, base + 32768, base + 49152,
                        rowA, rowB, gA, gB, l7, c);
        __syncthreads();
    }

    if (nt < 2) {
        // ---- v^T: bias+relu, transpose into smem split tiles, then block copy out ----
        #pragma unroll
        for (int mf = 0; mf < 4; mf++) {
            int row = wm * 64 + mf * 16 + (lane >> 2);
            #pragma unroll
            for (int nf = 0; nf < 4; nf++) {
                int col = wn * 32 + nf * 8 + ((lane & 3) << 1);   // local hid 0..127
                float b0 = __ldg(bv + nt * 128 + col), b1 = __ldg(bv + nt * 128 + col + 1);
                float v[4] = {fmaxf(c[mf][nf][0] + b0, 0.f), fmaxf(c[mf][nf][1] + b1, 0.f),
                              fmaxf(c[mf][nf][2] + b0, 0.f), fmaxf(c[mf][nf][3] + b1, 0.f)};
                int tok[4] = {row, row, row + 8, row + 8};
                int hid[4] = {col, col + 1, col, col + 1};
                #pragma unroll
                for (int t = 0; t < 4; t++) {
                    int tc = tok[t] >> 6;
                    uint32_t toff = (uint32_t)(tc * 16384) + tile_off(hid[t], tok[t] & 63);
                    __nv_bfloat16 h = __float2bfloat16(v[t]);
                    float lres = v[t] - __bfloat162float(h);
                    __nv_bfloat16 l = __float2bfloat16(lres);
                    *(__nv_bfloat16*)(sm + toff)         = h;
                    *(__nv_bfloat16*)(sm + 32768 + toff) = l;
                }
            }
        }
        __syncthreads();
        #pragma unroll
        for (int j = 0; j < 16; j++) {
            uint32_t u = (uint32_t)(tid + j * 256);      // 0..4095
            int hbuf = u >> 10;                           // 0:hi tc0, 1:hi tc1, 2:lo tc0, 3:lo tc1
            int tc = hbuf & 1;
            int isLo = hbuf >> 1;
            unsigned char* dst = (isLo ? g_vtlo : g_vthi) +
                                 (((size_t)mt * 2 + nt) * 2 + tc) * TILE_B + (size_t)(u & 1023) * 16;
            uint4 val = *(uint4*)(sm + (size_t)u * 16);
            *(uint4*)dst = val;
        }
    } else {
        const bool isq = nt < 6;
        unsigned char* dh = (isq ? g_qhi : g_khi) + (size_t)mt * 8 * TILE_B;
        unsigned char* dl = (isq ? g_qlo : g_klo) + (size_t)mt * 8 * TILE_B;
        const float* bias = isq ? bq : bk;
        int c0k = (isq ? (nt - 2) : (nt - 6)) * 128;
        #pragma unroll
        for (int mf = 0; mf < 4; mf++) {
            int row = wm * 64 + mf * 16 + (lane >> 2);
            #pragma unroll
            for (int nf = 0; nf < 4; nf++) {
                int col = c0k + wn * 32 + nf * 8 + ((lane & 3) << 1);
                float b0 = __ldg(bias + col), b1 = __ldg(bias + col + 1);
                float r0 = fmaxf(c[mf][nf][0] + b0, 0.f);
                float r1 = fmaxf(c[mf][nf][1] + b1, 0.f);
                float r2 = fmaxf(c[mf][nf][2] + b0, 0.f);
                float r3 = fmaxf(c[mf][nf][3] + b1, 0.f);
                int ch = col >> 6, kloc = col & 63;
                size_t tb = (size_t)ch * TILE_B;
                uint32_t lo0, hi0 = pack_hilo(r0, r1, lo0);
                uint32_t o0 = tile_off(row, kloc);
                *(uint32_t*)(dh + tb + o0) = hi0;
                *(uint32_t*)(dl + tb + o0) = lo0;
                uint32_t lo1, hi1 = pack_hilo(r2, r3, lo1);
                uint32_t o1 = tile_off(row + 8, kloc);
                *(uint32_t*)(dh + tb + o1) = hi1;
                *(uint32_t*)(dl + tb + o1) = lo1;
            }
        }
    }
}

// ================================================================================
// attn_fused: grid 2048 = (batch, half). 256 threads, ~112KB smem, 2 CTA/SM.
// Phases: GEMM1 scores(64x128) -> softmax -> GEMM2 ctx(64x256, smem) ->
//         GEMM3 out = relu(ctx@Wo + bo)  (out_tc fused; no ctx gmem round-trip)
// smem map (byte offsets):
//   phase1: [0,48K) stage: qHi 8K | qLo 8K | kHi 16K | kLo 16K ; [48K,80K) mask
//   phase2: [0,33.8K) scores fp32 [64][132]; att tiles [80K,112K):
//           hi tc0 8K | hi tc1 8K | lo tc0 8K | lo tc1 8K
//   phase3: [0,64K) vT: hi hb0 | hi hb1 | lo hb0 | lo hb1 (16K each)
//   phase3.5: [0,64K) ctx tiles: hi kc0..3 (8K each) | lo kc0..3
//   phase4: [64K,96K) Wo chunk: hi 16K | lo 16K
// ================================================================================
#define STG_Q   0
#define STG_K   16384
#define MSK_OFF 49152
#define ATT_OFF 81920
#define WO_OFF  65536
#define ATTN_SMEM 114688

__global__ __launch_bounds__(256, 2) void attn_fused(
    const float* __restrict__ mask, const float* __restrict__ bo,
    float* __restrict__ out, float* __restrict__ att_out)
{
    extern __shared__ char sm[];
    const int b = blockIdx.x >> 1;
    const int h = blockIdx.x & 1;
    const int tid = threadIdx.x, lane = tid & 31, wid = tid >> 5;
    const int wm = wid >> 2, wn = wid & 3;
    const int l15 = lane & 15, l7 = lane & 7;
    const int gA = lane >> 4, gB = (lane >> 3) & 1;
    const uint32_t S0 = smem_u32(sm);

    const unsigned char* qh = g_qhi + (size_t)b * 8 * TILE_B + (size_t)h * 8192;
    const unsigned char* ql = g_qlo + (size_t)b * 8 * TILE_B + (size_t)h * 8192;
    const unsigned char* kh = g_khi + (size_t)b * 8 * TILE_B;
    const unsigned char* kl = g_klo + (size_t)b * 8 * TILE_B;

    // ---------------- GEMM1: scores[64x128] = q_half @ k^T ----------------
    uint32_t rowA[2], rowB[4];
    #pragma unroll
    for (int mf = 0; mf < 2; mf++) rowA[mf] = (uint32_t)((wm * 32 + mf * 16 + l15) * 128);
    #pragma unroll
    for (int nf = 0; nf < 4; nf++) rowB[nf] = (uint32_t)((wn * 32 + nf * 8 + l7) * 128);

    float c[2][4][4];
    #pragma unroll
    for (int i = 0; i < 2; i++)
        #pragma unroll
        for (int j = 0; j < 4; j++)
            #pragma unroll
            for (int t = 0; t < 4; t++) c[i][j][t] = 0.f;

    // mask half -> smem (one-time, rides with chunk0's wait)
    {
        const unsigned char* mg =
            (const unsigned char*)(mask + (size_t)b * N_ * N_ + (size_t)h * 64 * N_);
        #pragma unroll
        for (int j = 0; j < 8; j++) {
            uint32_t o = (uint32_t)((tid + j * 256) * 16);
            CP16(S0 + MSK_OFF + o, mg + o);
        }
    }

    for (int ch = 0; ch < 8; ch++) {
        size_t src = (size_t)ch * TILE_B;
        // q half: 8K hi + 8K lo (contiguous sub-tile), k full: 16K + 16K
        #pragma unroll
        for (int j = 0; j < 2; j++) {
            uint32_t o = (uint32_t)((tid + j * 256) * 16);   // 0..8191
            CP16(S0 + STG_Q + o,        qh + src + o);
            CP16(S0 + STG_Q + 8192 + o, ql + src + o);
        }
        #pragma unroll
        for (int j = 0; j < 4; j++) {
            uint32_t o = (uint32_t)((tid + j * 256) * 16);   // 0..16383
            CP16(S0 + STG_K + o,         kh + src + o);
            CP16(S0 + STG_K + 16384 + o, kl + src + o);
        }
        CP_COMMIT();
        CP_WAIT0();
        __syncthreads();
        mma_block<2, 4>(S0 + STG_Q, S0 + STG_Q + 8192,
                        S0 + STG_K, S0 + STG_K + 16384, rowA, rowB, gA, gB, l7, c);
        __syncthreads();
    }

    // ---- fragments -> scores smem [64][132] ----
    float* scores = (float*)sm;
    #pragma unroll
    for (int mf = 0; mf < 2; mf++) {
        int row = wm * 32 + mf * 16 + (lane >> 2);
        #pragma unroll
        for (int nf = 0; nf < 4; nf++) {
            int col = wn * 32 + nf * 8 + ((lane & 3) << 1);
            *(float2*)(scores + row * 132 + col)       = make_float2(c[mf][nf][0], c[mf][nf][1]);
            *(float2*)(scores + (row + 8) * 132 + col) = make_float2(c[mf][nf][2], c[mf][nf][3]);
        }
    }
    __syncthreads();

    // ---- mask + softmax: 4 threads/row over 64 rows ----
    {
        int lr = tid >> 2;           // 0..63
        int seg = tid & 3;           // 32 cols each
        float* srow = scores + lr * 132 + seg * 32;
        const float* mrow = (const float*)(sm + MSK_OFF) + lr * 128 + seg * 32;
        float mx = -1e30f;
        float buf[32];
        #pragma unroll
        for (int i = 0; i < 8; i++) {
            float4 s = *(float4*)(srow + i * 4);
            float4 mk = *(const float4*)(mrow + i * 4);
            s.x = mk.x * (s.x + 1000.f) - 1000.f;
            s.y = mk.y * (s.y + 1000.f) - 1000.f;
            s.z = mk.z * (s.z + 1000.f) - 1000.f;
            s.w = mk.w * (s.w + 1000.f) - 1000.f;
            buf[i * 4 + 0] = s.x; buf[i * 4 + 1] = s.y;
            buf[i * 4 + 2] = s.z; buf[i * 4 + 3] = s.w;
            mx = fmaxf(mx, fmaxf(fmaxf(s.x, s.y), fmaxf(s.z, s.w)));
        }
        mx = fmaxf(mx, __shfl_xor_sync(0xFFFFFFFF, mx, 1));
        mx = fmaxf(mx, __shfl_xor_sync(0xFFFFFFFF, mx, 2));
        float sum = 0.f;
        #pragma unroll
        for (int i = 0; i < 32; i++) {
            buf[i] = __expf(buf[i] - mx);
            sum += buf[i];
        }
        sum += __shfl_xor_sync(0xFFFFFFFF, sum, 1);
        sum += __shfl_xor_sync(0xFFFFFFFF, sum, 2);
        float inv = 1.f / sum;
        float* arow = att_out + (size_t)b * N_ * N_ + (size_t)(h * 64 + lr) * N_ + seg * 32;
        char* attHi = sm + ATT_OFF;
        char* attLo = sm + ATT_OFF + 16384;
        #pragma unroll
        for (int i = 0; i < 8; i++) {
            int cc = seg * 32 + i * 4;
            float4 a = {buf[i*4+0] * inv, buf[i*4+1] * inv, buf[i*4+2] * inv, buf[i*4+3] * inv};
            *(float4*)(arow + i * 4) = a;
            uint2 hi, lo;
            hi.x = pack_hilo(a.x, a.y, lo.x);
            hi.y = pack_hilo(a.z, a.w, lo.y);
            int tc = cc >> 6;
            uint32_t off = (uint32_t)(tc * 8192) + tile_off(lr, cc & 63);
            *(uint2*)(attHi + off) = hi;
            *(uint2*)(attLo + off) = lo;
        }
    }

    // ---------------- GEMM2: ctx[64x256] = att @ v^T-tiles ----------------
    uint32_t rowA2[2], rowB2[8];
    #pragma unroll
    for (int mf = 0; mf < 2; mf++) rowA2[mf] = (uint32_t)((wm * 32 + mf * 16 + l15) * 128);
    #pragma unroll
    for (int nf = 0; nf < 8; nf++) rowB2[nf] = (uint32_t)(((wn & 1) * 64 + nf * 8 + l7) * 128);

    float d[2][8][4];
    #pragma unroll
    for (int i = 0; i < 2; i++)
        #pragma unroll
        for (int j = 0; j < 8; j++)
            #pragma unroll
            for (int t = 0; t < 4; t++) d[i][j][t] = 0.f;

    const int hb = wn >> 1;
    for (int tc = 0; tc < 2; tc++) {
        __syncthreads();   // att ready (tc0) / prev vT consumed (tc1)
        #pragma unroll
        for (int j = 0; j < 16; j++) {
            uint32_t u = (uint32_t)(tid + j * 256);    // 0..4095
            int hbuf = u >> 10;                         // 0:hi hb0 1:hi hb1 2:lo hb0 3:lo hb1
            int vhb = hbuf & 1, isLo = hbuf >> 1;
            const unsigned char* src = (isLo ? g_vtlo : g_vthi) +
                (((size_t)b * 2 + vhb) * 2 + tc) * TILE_B + (size_t)(u & 1023) * 16;
            CP16(S0 + (uint32_t)(hbuf * 16384) + (u & 1023) * 16, src);
        }
        CP_COMMIT();
        CP_WAIT0();
        __syncthreads();

        uint32_t aH = S0 + ATT_OFF + (uint32_t)(tc * 8192);
        uint32_t aL = aH + 16384;
        uint32_t bH = S0 + (uint32_t)(hb * 16384);
        uint32_t bL = bH + 32768;
        mma_block<2, 8>(aH, aL, bH, bL, rowA2, rowB2, gA, gB, l7, d);
    }
    __syncthreads();   // all GEMM2 reads of vT done before overwriting with ctx

    // ---- ctx -> split tiles in smem [0,64K): hi kc0..3 | lo kc0..3 ----
    #pragma unroll
    for (int mf = 0; mf < 2; mf++) {
        int row = wm * 32 + mf * 16 + (lane >> 2);
        #pragma unroll
        for (int nf = 0; nf < 8; nf++) {
            int col = wn * 64 + nf * 8 + ((lane & 3) << 1);
            int kc = col >> 6, kloc = col & 63;
            uint32_t lo0, hi0 = pack_hilo(d[mf][nf][0], d[mf][nf][1], lo0);
            uint32_t o0 = (uint32_t)(kc * 8192) + tile_off(row, kloc);
            *(uint32_t*)(sm + o0)         = hi0;
            *(uint32_t*)(sm + 32768 + o0) = lo0;
            uint32_t lo1, hi1 = pack_hilo(d[mf][nf][2], d[mf][nf][3], lo1);
            uint32_t o1 = (uint32_t)(kc * 8192) + tile_off(row + 8, kloc);
            *(uint32_t*)(sm + o1)         = hi1;
            *(uint32_t*)(sm + 32768 + o1) = lo1;
        }
    }
    __syncthreads();

    // ---------------- GEMM3: out = relu(ctx @ Wo + bo) ----------------
    for (int nt = 0; nt < 2; nt++) {
        float e[2][4][4];
        #pragma unroll
        for (int i = 0; i < 2; i++)
            #pragma unroll
            for (int j = 0; j < 4; j++)
                #pragma unroll
                for (int t = 0; t < 4; t++) e[i][j][t] = 0.f;

        const unsigned char* Wh = g_whi + (size_t)(10 + nt) * 4 * TILE_B;
        const unsigned char* Wl = g_wlo + (size_t)(10 + nt) * 4 * TILE_B;

        for (int kc = 0; kc < 4; kc++) {
            // load Wo chunk (16K hi + 16K lo) into [64K,96K)
            #pragma unroll
            for (int j = 0; j < 8; j++) {
                uint32_t u = (uint32_t)(tid + j * 256);  // 0..2047
                int isLo = u >> 10;
                const unsigned char* src = (isLo ? Wl : Wh) +
                    (size_t)kc * TILE_B + (size_t)(u & 1023) * 16;
                CP16(S0 + WO_OFF + (uint32_t)(isLo * 16384) + (u & 1023) * 16, src);
            }
            CP_COMMIT();
            CP_WAIT0();
            __syncthreads();
            mma_block<2, 4>(S0 + (uint32_t)(kc * 8192), S0 + 32768 + (uint32_t)(kc * 8192),
                            S0 + WO_OFF, S0 + WO_OFF + 16384, rowA2, rowB, gA, gB, l7, e);
            __syncthreads();
        }

        int c0 = nt * 128;
        #pragma unroll
        for (int mf = 0; mf < 2; mf++) {
            int row = h * 64 + wm * 32 + mf * 16 + (lane >> 2);
            #pragma unroll
            for (int nf = 0; nf < 4; nf++) {
                int col = c0 + wn * 32 + nf * 8 + ((lane & 3) << 1);
                float b0 = __ldg(bo + col), b1 = __ldg(bo + col + 1);
                float2 o0 = {fmaxf(e[mf][nf][0] + b0, 0.f), fmaxf(e[mf][nf][1] + b1, 0.f)};
                float2 o1 = {fmaxf(e[mf][nf][2] + b0, 0.f), fmaxf(e[mf][nf][3] + b1, 0.f)};
                *(float2*)(out + (size_t)(b * 128 + row) * DOUT_ + col)     = o0;
                *(float2*)(out + (size_t)(b * 128 + row + 8) * DOUT_ + col) = o1;
            }
        }
    }
}

// ================================================================================
// Launch
// ================================================================================
extern "C" void kernel_launch(void* const* d_in, const int* in_sizes, int n_in,
                              void* d_out, int out_size)
{
    const float* x    = (const float*)d_in[0];
    const float* mask = (const float*)d_in[1];
    const float* Wv   = (const float*)d_in[2];
    const float* bv   = (const float*)d_in[3];
    const float* Wq   = (const float*)d_in[4];
    const float* bq   = (const float*)d_in[5];
    const float* Wk   = (const float*)d_in[6];
    const float* bk   = (const float*)d_in[7];
    const float* Wo   = (const float*)d_in[8];
    const float* bo   = (const float*)d_in[9];

    float* out     = (float*)d_out;
    float* att_out = out + (size_t)B_ * N_ * DOUT_;

    cudaFuncSetAttribute(qkv_tc,     cudaFuncAttributeMaxDynamicSharedMemorySize, 65536);
    cudaFuncSetAttribute(attn_fused, cudaFuncAttributeMaxDynamicSharedMemorySize, ATTN_SMEM);

    split_x_kernel<<<1024, 256>>>(x);
    split_w_kernel<<<12, 256>>>(Wv, Wq, Wk, Wo);
    qkv_tc<<<dim3(10, 1024), 256, 65536>>>(bv, bq, bk);
    attn_fused<<<2048, 256, ATTN_SMEM>>>(mask, bo, out, att_out);
}

// round 10
// speedup vs baseline: 1.0696x; 1.0696x over previous
#include <cuda_runtime.h>
#include <cuda_bf16.h>
#include <cstdint>

#define B_    1024
#define N_    128
#define DIN_  256
#define HID_  256
#define DOUT_ 256
#define KDIM_ 512

#define TILE_B 16384   // one [128 rows][64 k] split-bf16 tile (swizzled)

// ---------------- scratch (static device globals; no allocation) ----------------
__device__ unsigned char g_xhi[(size_t)1024 * 4 * TILE_B];
__device__ unsigned char g_xlo[(size_t)1024 * 4 * TILE_B];
__device__ unsigned char g_whi[(size_t)12 * 4 * TILE_B];
__device__ unsigned char g_wlo[(size_t)12 * 4 * TILE_B];
__device__ unsigned char g_qhi[(size_t)1024 * 8 * TILE_B];
__device__ unsigned char g_qlo[(size_t)1024 * 8 * TILE_B];
__device__ unsigned char g_khi[(size_t)1024 * 8 * TILE_B];
__device__ unsigned char g_klo[(size_t)1024 * 8 * TILE_B];
// v^T tiles: per batch: (hb 0..1) x (tc 0..1), index = (b*2+hb)*2+tc
__device__ unsigned char g_vthi[(size_t)1024 * 4 * TILE_B];
__device__ unsigned char g_vtlo[(size_t)1024 * 4 * TILE_B];

// ================================================================================
// helpers
// ================================================================================
__device__ __forceinline__ uint32_t smem_u32(const void* p) {
    uint32_t a;
    asm("{ .reg .u64 t; cvta.to.shared.u64 t, %1; cvt.u32.u64 %0, t; }" : "=r"(a) : "l"(p));
    return a;
}
__device__ __forceinline__ void ldm_x4(uint32_t* r, uint32_t addr) {
    asm volatile("ldmatrix.sync.aligned.m8n8.x4.shared.b16 {%0,%1,%2,%3}, [%4];"
                 : "=r"(r[0]), "=r"(r[1]), "=r"(r[2]), "=r"(r[3]) : "r"(addr));
}
__device__ __forceinline__ void ldm_x2(uint32_t* r, uint32_t addr) {
    asm volatile("ldmatrix.sync.aligned.m8n8.x2.shared.b16 {%0,%1}, [%2];"
                 : "=r"(r[0]), "=r"(r[1]) : "r"(addr));
}
__device__ __forceinline__ void mma_bf16(float* c, const uint32_t* a, const uint32_t* b) {
    asm volatile(
        "mma.sync.aligned.m16n8k16.row.col.f32.bf16.bf16.f32 "
        "{%0,%1,%2,%3}, {%4,%5,%6,%7}, {%8,%9}, {%0,%1,%2,%3};"
        : "+f"(c[0]), "+f"(c[1]), "+f"(c[2]), "+f"(c[3])
        : "r"(a[0]), "r"(a[1]), "r"(a[2]), "r"(a[3]), "r"(b[0]), "r"(b[1]));
}
__device__ __forceinline__ uint32_t pack_hilo(float x, float y, uint32_t& lo_out) {
    __nv_bfloat162 h = __floats2bfloat162_rn(x, y);
    float lx = x - __low2float(h);
    float ly = y - __high2float(h);
    __nv_bfloat162 l = __floats2bfloat162_rn(lx, ly);
    lo_out = *reinterpret_cast<uint32_t*>(&l);
    return *reinterpret_cast<uint32_t*>(&h);
}
__device__ __forceinline__ uint32_t tile_off(int row, int k) {
    int g = k >> 3;
    return (uint32_t)(row * 128 + ((g ^ (row & 7)) << 4) + ((k & 7) << 1));
}

#define CP16(dst_s, src_g) \
    asm volatile("cp.async.cg.shared.global [%0], [%1], 16;" :: "r"(dst_s), "l"(src_g) : "memory")
#define CP_COMMIT() asm volatile("cp.async.commit_group;" ::: "memory")
#define CP_WAIT0()  asm volatile("cp.async.wait_group 0;" ::: "memory")
#define CP_WAIT1()  asm volatile("cp.async.wait_group 1;" ::: "memory")

// ================================================================================
// fused 3-pass MMA block (all operands resident): MF x NF frags
// ================================================================================
template<int MF, int NF>
__device__ __forceinline__ void mma_block(
    uint32_t aHi, uint32_t aLo, uint32_t bHi, uint32_t bLo,
    const uint32_t* rowA, const uint32_t* rowB,
    int gA, int gB, int l7, float (*c)[NF][4])
{
    #pragma unroll
    for (int ks = 0; ks < 4; ks++) {
        uint32_t pa = (uint32_t)((((ks << 1) + gA) ^ l7) << 4);
        uint32_t pb = (uint32_t)((((ks << 1) + gB) ^ l7) << 4);
        uint32_t a[MF][4];
        #pragma unroll
        for (int mf = 0; mf < MF; mf++) ldm_x4(a[mf], aHi + rowA[mf] + pa);
        #pragma unroll
        for (int nf = 0; nf < NF; nf++) {
            uint32_t b[2]; ldm_x2(b, bHi + rowB[nf] + pb);
            #pragma unroll
            for (int mf = 0; mf < MF; mf++) mma_bf16(c[mf][nf], a[mf], b);
        }
        #pragma unroll
        for (int nf = 0; nf < NF; nf++) {
            uint32_t b[2]; ldm_x2(b, bLo + rowB[nf] + pb);
            #pragma unroll
            for (int mf = 0; mf < MF; mf++) mma_bf16(c[mf][nf], a[mf], b);
        }
        #pragma unroll
        for (int mf = 0; mf < MF; mf++) ldm_x4(a[mf], aLo + rowA[mf] + pa);
        #pragma unroll
        for (int nf = 0; nf < NF; nf++) {
            uint32_t b[2]; ldm_x2(b, bHi + rowB[nf] + pb);
            #pragma unroll
            for (int mf = 0; mf < MF; mf++) mma_bf16(c[mf][nf], a[mf], b);
        }
    }
}

// single pass: c += A(aBuf) x B(bBuf)
template<int MF, int NF>
__device__ __forceinline__ void mma_pass(
    uint32_t aBuf, uint32_t bBuf,
    const uint32_t* rowA, const uint32_t* rowB,
    int gA, int gB, int l7, float (*c)[NF][4])
{
    #pragma unroll
    for (int ks = 0; ks < 4; ks++) {
        uint32_t pa = (uint32_t)((((ks << 1) + gA) ^ l7) << 4);
        uint32_t pb = (uint32_t)((((ks << 1) + gB) ^ l7) << 4);
        uint32_t a[MF][4];
        #pragma unroll
        for (int mf = 0; mf < MF; mf++) ldm_x4(a[mf], aBuf + rowA[mf] + pa);
        #pragma unroll
        for (int nf = 0; nf < NF; nf++) {
            uint32_t b[2]; ldm_x2(b, bBuf + rowB[nf] + pb);
            #pragma unroll
            for (int mf = 0; mf < MF; mf++) mma_bf16(c[mf][nf], a[mf], b);
        }
    }
}

// ================================================================================
// split_x / split_w
// ================================================================================
__global__ __launch_bounds__(256) void split_x_kernel(const float* __restrict__ x)
{
    const int mt = blockIdx.x, tid = threadIdx.x;
    const float* A = x + (size_t)mt * 128 * DIN_;
    unsigned char* dh = g_xhi + (size_t)mt * 4 * TILE_B;
    unsigned char* dl = g_xlo + (size_t)mt * 4 * TILE_B;
    #pragma unroll
    for (int i = 0; i < 16; i++) {
        int G = tid + i * 256;
        int m = G >> 5, gg = G & 31;
        int ch = gg >> 3, g = gg & 7;
        const float* p = A + (size_t)m * DIN_ + gg * 8;
        float4 v0 = *(const float4*)p, v1 = *(const float4*)(p + 4);
        uint4 hi, lo;
        hi.x = pack_hilo(v0.x, v0.y, lo.x);
        hi.y = pack_hilo(v0.z, v0.w, lo.y);
        hi.z = pack_hilo(v1.x, v1.y, lo.z);
        hi.w = pack_hilo(v1.z, v1.w, lo.w);
        uint32_t off = (uint32_t)(ch * TILE_B + m * 128 + ((g ^ (m & 7)) << 4));
        *(uint4*)(dh + off) = hi;
        *(uint4*)(dl + off) = lo;
    }
}

__global__ __launch_bounds__(256) void split_w_kernel(
    const float* __restrict__ Wv, const float* __restrict__ Wq,
    const float* __restrict__ Wk, const float* __restrict__ Wo)
{
    __shared__ float wst[64 * 132];
    const int tt = blockIdx.x, tid = threadIdx.x;
    const float* W; int wld, c0;
    if (tt < 2)       { W = Wv; wld = HID_;  c0 = tt * 128; }
    else if (tt < 6)  { W = Wq; wld = KDIM_; c0 = (tt - 2) * 128; }
    else if (tt < 10) { W = Wk; wld = KDIM_; c0 = (tt - 6) * 128; }
    else              { W = Wo; wld = DOUT_; c0 = (tt - 10) * 128; }

    unsigned char* dh = g_whi + (size_t)tt * 4 * TILE_B;
    unsigned char* dl = g_wlo + (size_t)tt * 4 * TILE_B;

    for (int ch = 0; ch < 4; ch++) {
        #pragma unroll
        for (int i = 0; i < 8; i++) {
            int idx = tid + i * 256;
            int kr = idx >> 5, nq = (idx & 31) << 2;
            *(float4*)(wst + kr * 132 + nq) =
                *(const float4*)(W + (size_t)(ch * 64 + kr) * wld + c0 + nq);
        }
        __syncthreads();
        {
            int n = tid & 127, ks2 = tid >> 7;
            #pragma unroll
            for (int j = 0; j < 4; j++) {
                int g = ks2 * 4 + j, kb = g * 8;
                float v[8];
                #pragma unroll
                for (int t = 0; t < 8; t++) v[t] = wst[(kb + t) * 132 + n];
                uint4 hi, lo;
                hi.x = pack_hilo(v[0], v[1], lo.x);
                hi.y = pack_hilo(v[2], v[3], lo.y);
                hi.z = pack_hilo(v[4], v[5], lo.z);
                hi.w = pack_hilo(v[6], v[7], lo.w);
                uint32_t off = (uint32_t)(ch * TILE_B + n * 128 + ((g ^ (n & 7)) << 4));
                *(uint4*)(dh + off) = hi;
                *(uint4*)(dl + off) = lo;
            }
        }
        __syncthreads();
    }
}

// ================================================================================
// qkv: grid (10, 1024), 256 threads, 96KB smem (3x32KB rotating), 2 CTA/SM.
// X=(aHi|bHi) Y=(aLo|bLo); pass1 = aHi*bHi uses X only, so X(ch+1) stages behind
// the whole chunk and Y(ch+1) behind pass1 of the next chunk.
// ================================================================================
#define QKV_SMEM 98304

__global__ __launch_bounds__(256, 2) void qkv_tc(
    const float* __restrict__ bv, const float* __restrict__ bq, const float* __restrict__ bk)
{
    extern __shared__ char sm[];
    const int nt = blockIdx.x, mt = blockIdx.y;
    const int tid = threadIdx.x, lane = tid & 31, wid = tid >> 5;
    const int wm = wid >> 2, wn = wid & 3;
    const int l15 = lane & 15, l7 = lane & 7;
    const int gA = lane >> 4, gB = (lane >> 3) & 1;
    const uint32_t S0 = smem_u32(sm);

    uint32_t rowA[4], rowB[4];
    #pragma unroll
    for (int mf = 0; mf < 4; mf++) rowA[mf] = (uint32_t)((wm * 64 + mf * 16 + l15) * 128);
    #pragma unroll
    for (int nf = 0; nf < 4; nf++) rowB[nf] = (uint32_t)((wn * 32 + nf * 8 + l7) * 128);

    float c[4][4][4];
    #pragma unroll
    for (int i = 0; i < 4; i++)
        #pragma unroll
        for (int j = 0; j < 4; j++)
            #pragma unroll
            for (int t = 0; t < 4; t++) c[i][j][t] = 0.f;

    const unsigned char* Ah = g_xhi + (size_t)mt * 4 * TILE_B;
    const unsigned char* Al = g_xlo + (size_t)mt * 4 * TILE_B;
    const unsigned char* Bh = g_whi + (size_t)nt * 4 * TILE_B;
    const unsigned char* Bl = g_wlo + (size_t)nt * 4 * TILE_B;

    auto stageX = [&](uint32_t buf, int ch) {
        size_t src = (size_t)ch * TILE_B;
        #pragma unroll
        for (int j = 0; j < 4; j++) {
            uint32_t o = (uint32_t)((tid + j * 256) * 16);
            CP16(buf + o,         Ah + src + o);
            CP16(buf + 16384 + o, Bh + src + o);
        }
    };
    auto stageY = [&](uint32_t buf, int ch) {
        size_t src = (size_t)ch * TILE_B;
        #pragma unroll
        for (int j = 0; j < 4; j++) {
            uint32_t o = (uint32_t)((tid + j * 256) * 16);
            CP16(buf + o,         Al + src + o);
            CP16(buf + 16384 + o, Bl + src + o);
        }
    };

    uint32_t bufs[3] = {S0, S0 + 32768, S0 + 65536};
    int bx = 0, by = 1, bn = 2;

    stageX(bufs[0], 0); CP_COMMIT();
    stageY(bufs[1], 0); CP_COMMIT();

    for (int ch = 0; ch < 4; ch++) {
        CP_WAIT1();                 // X(ch) ready (Y(ch) may still be in flight)
        __syncthreads();
        if (ch < 3) { stageX(bufs[bn], ch + 1); CP_COMMIT(); }
        // pass1: aHi x bHi (X only)
        mma_pass<4, 4>(bufs[bx], bufs[bx] + 16384, rowA, rowB, gA, gB, l7, c);
        if (ch < 3) CP_WAIT1(); else CP_WAIT0();   // Y(ch) ready
        __syncthreads();
        // pass2: aHi x bLo ; pass3: aLo x bHi
        mma_pass<4, 4>(bufs[bx], bufs[by] + 16384, rowA, rowB, gA, gB, l7, c);
        mma_pass<4, 4>(bufs[by], bufs[bx] + 16384, rowA, rowB, gA, gB, l7, c);
        __syncthreads();            // bx free for Y(ch+1)
        if (ch < 3) { stageY(bufs[bx], ch + 1); CP_COMMIT(); }
        int t = bn; bn = by; by = bx; bx = t;
    }

    if (nt < 2) {
        // ---- v^T: bias+relu, transpose into smem split tiles, then block copy out ----
        #pragma unroll
        for (int mf = 0; mf < 4; mf++) {
            int row = wm * 64 + mf * 16 + (lane >> 2);
            #pragma unroll
            for (int nf = 0; nf < 4; nf++) {
                int col = wn * 32 + nf * 8 + ((lane & 3) << 1);   // local hid 0..127
                float b0 = __ldg(bv + nt * 128 + col), b1 = __ldg(bv + nt * 128 + col + 1);
                float v[4] = {fmaxf(c[mf][nf][0] + b0, 0.f), fmaxf(c[mf][nf][1] + b1, 0.f),
                              fmaxf(c[mf][nf][2] + b0, 0.f), fmaxf(c[mf][nf][3] + b1, 0.f)};
                int tok[4] = {row, row, row + 8, row + 8};
                int hid[4] = {col, col + 1, col, col + 1};
                #pragma unroll
                for (int t = 0; t < 4; t++) {
                    int tc = tok[t] >> 6;
                    uint32_t toff = (uint32_t)(tc * 16384) + tile_off(hid[t], tok[t] & 63);
                    __nv_bfloat16 h = __float2bfloat16(v[t]);
                    float lres = v[t] - __bfloat162float(h);
                    __nv_bfloat16 l = __float2bfloat16(lres);
                    *(__nv_bfloat16*)(sm + toff)         = h;
                    *(__nv_bfloat16*)(sm + 32768 + toff) = l;
                }
            }
        }
        __syncthreads();
        #pragma unroll
        for (int j = 0; j < 16; j++) {
            uint32_t u = (uint32_t)(tid + j * 256);      // 0..4095
            int hbuf = u >> 10;                           // 0:hi tc0, 1:hi tc1, 2:lo tc0, 3:lo tc1
            int tc = hbuf & 1;
            int isLo = hbuf >> 1;
            unsigned char* dst = (isLo ? g_vtlo : g_vthi) +
                                 (((size_t)mt * 2 + nt) * 2 + tc) * TILE_B + (size_t)(u & 1023) * 16;
            uint4 val = *(uint4*)(sm + (size_t)u * 16);
            *(uint4*)dst = val;
        }
    } else {
        const bool isq = nt < 6;
        unsigned char* dh = (isq ? g_qhi : g_khi) + (size_t)mt * 8 * TILE_B;
        unsigned char* dl = (isq ? g_qlo : g_klo) + (size_t)mt * 8 * TILE_B;
        const float* bias = isq ? bq : bk;
        int c0k = (isq ? (nt - 2) : (nt - 6)) * 128;
        #pragma unroll
        for (int mf = 0; mf < 4; mf++) {
            int row = wm * 64 + mf * 16 + (lane >> 2);
            #pragma unroll
            for (int nf = 0; nf < 4; nf++) {
                int col = c0k + wn * 32 + nf * 8 + ((lane & 3) << 1);
                float b0 = __ldg(bias + col), b1 = __ldg(bias + col + 1);
                float r0 = fmaxf(c[mf][nf][0] + b0, 0.f);
                float r1 = fmaxf(c[mf][nf][1] + b1, 0.f);
                float r2 = fmaxf(c[mf][nf][2] + b0, 0.f);
                float r3 = fmaxf(c[mf][nf][3] + b1, 0.f);
                int ch = col >> 6, kloc = col & 63;
                size_t tb = (size_t)ch * TILE_B;
                uint32_t lo0, hi0 = pack_hilo(r0, r1, lo0);
                uint32_t o0 = tile_off(row, kloc);
                *(uint32_t*)(dh + tb + o0) = hi0;
                *(uint32_t*)(dl + tb + o0) = lo0;
                uint32_t lo1, hi1 = pack_hilo(r2, r3, lo1);
                uint32_t o1 = tile_off(row + 8, kloc);
                *(uint32_t*)(dh + tb + o1) = hi1;
                *(uint32_t*)(dl + tb + o1) = lo1;
            }
        }
    }
}

// ================================================================================
// attn_fused: grid 2048 = (batch, half). 256 threads, 100KB smem, 2 CTA/SM.
// GEMM1 fully double-buffered (2 x 48KB sets); mask load deferred behind frag-write.
// smem (byte offsets):
//   GEMM1:  set0 [0,48K): qHi 8K | qLo 8K | kHi 16K | kLo 16K ; set1 [48K,96K)
//   post:   scores f32 [0,33792); att tiles [34816,67584); mask [69632,102400)
//   GEMM2:  vT hi hb0 [0,16K) hb1 [16K,32K); vT lo hb0 [69632,..) hb1 [86016,..)
//   GEMM3:  ctx hi [34816,67584), ctx lo [0,32768); Wo hi [69632,..), lo [86016,..)
// ================================================================================
#define ATT2    34816
#define MSK2    69632
#define WLO2    86016
#define ATTN_SMEM 102400

__global__ __launch_bounds__(256, 2) void attn_fused(
    const float* __restrict__ mask, const float* __restrict__ bo,
    float* __restrict__ out, float* __restrict__ att_out)
{
    extern __shared__ char sm[];
    const int b = blockIdx.x >> 1;
    const int h = blockIdx.x & 1;
    const int tid = threadIdx.x, lane = tid & 31, wid = tid >> 5;
    const int wm = wid >> 2, wn = wid & 3;
    const int l15 = lane & 15, l7 = lane & 7;
    const int gA = lane >> 4, gB = (lane >> 3) & 1;
    const uint32_t S0 = smem_u32(sm);

    const unsigned char* qh = g_qhi + (size_t)b * 8 * TILE_B + (size_t)h * 8192;
    const unsigned char* ql = g_qlo + (size_t)b * 8 * TILE_B + (size_t)h * 8192;
    const unsigned char* kh = g_khi + (size_t)b * 8 * TILE_B;
    const unsigned char* kl = g_klo + (size_t)b * 8 * TILE_B;

    uint32_t rowA[2], rowB[4];
    #pragma unroll
    for (int mf = 0; mf < 2; mf++) rowA[mf] = (uint32_t)((wm * 32 + mf * 16 + l15) * 128);
    #pragma unroll
    for (int nf = 0; nf < 4; nf++) rowB[nf] = (uint32_t)((wn * 32 + nf * 8 + l7) * 128);

    float c[2][4][4];
    #pragma unroll
    for (int i = 0; i < 2; i++)
        #pragma unroll
        for (int j = 0; j < 4; j++)
            #pragma unroll
            for (int t = 0; t < 4; t++) c[i][j][t] = 0.f;

    auto stage_set = [&](uint32_t base, int ch) {
        size_t src = (size_t)ch * TILE_B;
        #pragma unroll
        for (int j = 0; j < 2; j++) {
            uint32_t o = (uint32_t)((tid + j * 256) * 16);   // 0..8191
            CP16(base + o,        qh + src + o);
            CP16(base + 8192 + o, ql + src + o);
        }
        #pragma unroll
        for (int j = 0; j < 4; j++) {
            uint32_t o = (uint32_t)((tid + j * 256) * 16);   // 0..16383
            CP16(base + 16384 + o, kh + src + o);
            CP16(base + 32768 + o, kl + src + o);
        }
    };

    // ---------------- GEMM1: double-buffered over 8 chunks ----------------
    stage_set(S0, 0); CP_COMMIT();
    for (int ch = 0; ch < 8; ch++) {
        if (ch < 7) { stage_set(S0 + (uint32_t)((1 - (ch & 1)) * 49152), ch + 1); CP_COMMIT(); }
        if (ch < 7) CP_WAIT1(); else CP_WAIT0();
        __syncthreads();
        uint32_t s = S0 + (uint32_t)((ch & 1) * 49152);
        mma_block<2, 4>(s, s + 8192, s + 16384, s + 32768, rowA, rowB, gA, gB, l7, c);
        __syncthreads();
    }

    // ---- deferred mask load (hidden behind fragment write) ----
    {
        const unsigned char* mg =
            (const unsigned char*)(mask + (size_t)b * N_ * N_ + (size_t)h * 64 * N_);
        #pragma unroll
        for (int j = 0; j < 8; j++) {
            uint32_t o = (uint32_t)((tid + j * 256) * 16);   // 0..32767
            CP16(S0 + MSK2 + o, mg + o);
        }
        CP_COMMIT();
    }

    // ---- fragments -> scores smem [64][132] ----
    float* scores = (float*)sm;
    #pragma unroll
    for (int mf = 0; mf < 2; mf++) {
        int row = wm * 32 + mf * 16 + (lane >> 2);
        #pragma unroll
        for (int nf = 0; nf < 4; nf++) {
            int col = wn * 32 + nf * 8 + ((lane & 3) << 1);
            *(float2*)(scores + row * 132 + col)       = make_float2(c[mf][nf][0], c[mf][nf][1]);
            *(float2*)(scores + (row + 8) * 132 + col) = make_float2(c[mf][nf][2], c[mf][nf][3]);
        }
    }
    CP_WAIT0();
    __syncthreads();

    // ---- mask + softmax: 4 threads/row over 64 rows ----
    {
        int lr = tid >> 2;           // 0..63
        int seg = tid & 3;           // 32 cols each
        float* srow = scores + lr * 132 + seg * 32;
        const float* mrow = (const float*)(sm + MSK2) + lr * 128 + seg * 32;
        float mx = -1e30f;
        float buf[32];
        #pragma unroll
        for (int i = 0; i < 8; i++) {
            float4 s = *(float4*)(srow + i * 4);
            float4 mk = *(const float4*)(mrow + i * 4);
            s.x = mk.x * (s.x + 1000.f) - 1000.f;
            s.y = mk.y * (s.y + 1000.f) - 1000.f;
            s.z = mk.z * (s.z + 1000.f) - 1000.f;
            s.w = mk.w * (s.w + 1000.f) - 1000.f;
            buf[i * 4 + 0] = s.x; buf[i * 4 + 1] = s.y;
            buf[i * 4 + 2] = s.z; buf[i * 4 + 3] = s.w;
            mx = fmaxf(mx, fmaxf(fmaxf(s.x, s.y), fmaxf(s.z, s.w)));
        }
        mx = fmaxf(mx, __shfl_xor_sync(0xFFFFFFFF, mx, 1));
        mx = fmaxf(mx, __shfl_xor_sync(0xFFFFFFFF, mx, 2));
        float sum = 0.f;
        #pragma unroll
        for (int i = 0; i < 32; i++) {
            buf[i] = __expf(buf[i] - mx);
            sum += buf[i];
        }
        sum += __shfl_xor_sync(0xFFFFFFFF, sum, 1);
        sum += __shfl_xor_sync(0xFFFFFFFF, sum, 2);
        float inv = 1.f / sum;
        float* arow = att_out + (size_t)b * N_ * N_ + (size_t)(h * 64 + lr) * N_ + seg * 32;
        char* attHi = sm + ATT2;
        char* attLo = sm + ATT2 + 16384;
        #pragma unroll
        for (int i = 0; i < 8; i++) {
            int cc = seg * 32 + i * 4;
            float4 a = {buf[i*4+0] * inv, buf[i*4+1] * inv, buf[i*4+2] * inv, buf[i*4+3] * inv};
            *(float4*)(arow + i * 4) = a;
            uint2 hi, lo;
            hi.x = pack_hilo(a.x, a.y, lo.x);
            hi.y = pack_hilo(a.z, a.w, lo.y);
            int tc = cc >> 6;
            uint32_t off = (uint32_t)(tc * 8192) + tile_off(lr, cc & 63);
            *(uint2*)(attHi + off) = hi;
            *(uint2*)(attLo + off) = lo;
        }
    }

    // ---------------- GEMM2: ctx[64x256] = att @ v^T-tiles ----------------
    uint32_t rowA2[2], rowB2[8];
    #pragma unroll
    for (int mf = 0; mf < 2; mf++) rowA2[mf] = (uint32_t)((wm * 32 + mf * 16 + l15) * 128);
    #pragma unroll
    for (int nf = 0; nf < 8; nf++) rowB2[nf] = (uint32_t)(((wn & 1) * 64 + nf * 8 + l7) * 128);

    float d[2][8][4];
    #pragma unroll
    for (int i = 0; i < 2; i++)
        #pragma unroll
        for (int j = 0; j < 8; j++)
            #pragma unroll
            for (int t = 0; t < 4; t++) d[i][j][t] = 0.f;

    const int hb = wn >> 1;
    for (int tc = 0; tc < 2; tc++) {
        __syncthreads();   // att/scores/mask regions safe to reuse; prev vT consumed
        #pragma unroll
        for (int j = 0; j < 16; j++) {
            uint32_t u = (uint32_t)(tid + j * 256);    // 0..4095
            int hbuf = u >> 10;                         // 0:hi hb0 1:hi hb1 2:lo hb0 3:lo hb1
            int vhb = hbuf & 1, isLo = hbuf >> 1;
            const unsigned char* src = (isLo ? g_vtlo : g_vthi) +
                (((size_t)b * 2 + vhb) * 2 + tc) * TILE_B + (size_t)(u & 1023) * 16;
            uint32_t dst = isLo ? (S0 + MSK2 + (uint32_t)(vhb * 16384))
                                : (S0 + (uint32_t)(vhb * 16384));
            CP16(dst + (u & 1023) * 16, src);
        }
        CP_COMMIT();
        CP_WAIT0();
        __syncthreads();

        uint32_t aH = S0 + ATT2 + (uint32_t)(tc * 8192);
        uint32_t aL = aH + 16384;
        uint32_t bH = S0 + (uint32_t)(hb * 16384);
        uint32_t bL = S0 + MSK2 + (uint32_t)(hb * 16384);
        mma_block<2, 8>(aH, aL, bH, bL, rowA2, rowB2, gA, gB, l7, d);
    }
    __syncthreads();   // all GEMM2 reads done before ctx overwrite

    // ---- ctx -> split tiles: hi at ATT2 (+kc*8K), lo at 0 (+kc*8K) ----
    #pragma unroll
    for (int mf = 0; mf < 2; mf++) {
        int row = wm * 32 + mf * 16 + (lane >> 2);
        #pragma unroll
        for (int nf = 0; nf < 8; nf++) {
            int col = wn * 64 + nf * 8 + ((lane & 3) << 1);
            int kc = col >> 6, kloc = col & 63;
            uint32_t lo0, hi0 = pack_hilo(d[mf][nf][0], d[mf][nf][1], lo0);
            uint32_t o0 = (uint32_t)(kc * 8192) + tile_off(row, kloc);
            *(uint32_t*)(sm + ATT2 + o0) = hi0;
            *(uint32_t*)(sm + o0)        = lo0;
            uint32_t lo1, hi1 = pack_hilo(d[mf][nf][2], d[mf][nf][3], lo1);
            uint32_t o1 = (uint32_t)(kc * 8192) + tile_off(row + 8, kloc);
            *(uint32_t*)(sm + ATT2 + o1) = hi1;
            *(uint32_t*)(sm + o1)        = lo1;
        }
    }
    __syncthreads();

    // ---------------- GEMM3: out = relu(ctx @ Wo + bo) ----------------
    for (int nt = 0; nt < 2; nt++) {
        float e[2][4][4];
        #pragma unroll
        for (int i = 0; i < 2; i++)
            #pragma unroll
            for (int j = 0; j < 4; j++)
                #pragma unroll
                for (int t = 0; t < 4; t++) e[i][j][t] = 0.f;

        const unsigned char* Wh = g_whi + (size_t)(10 + nt) * 4 * TILE_B;
        const unsigned char* Wl = g_wlo + (size_t)(10 + nt) * 4 * TILE_B;

        for (int kc = 0; kc < 4; kc++) {
            #pragma unroll
            for (int j = 0; j < 4; j++) {
                uint32_t o = (uint32_t)((tid + j * 256) * 16);   // 0..16383
                CP16(S0 + MSK2 + o, Wh + (size_t)kc * TILE_B + o);
                CP16(S0 + WLO2 + o, Wl + (size_t)kc * TILE_B + o);
            }
            CP_COMMIT();
            CP_WAIT0();
            __syncthreads();
            mma_block<2, 4>(S0 + ATT2 + (uint32_t)(kc * 8192), S0 + (uint32_t)(kc * 8192),
                            S0 + MSK2, S0 + WLO2, rowA2, rowB, gA, gB, l7, e);
            __syncthreads();
        }

        int c0 = nt * 128;
        #pragma unroll
        for (int mf = 0; mf < 2; mf++) {
            int row = h * 64 + wm * 32 + mf * 16 + (lane >> 2);
            #pragma unroll
            for (int nf = 0; nf < 4; nf++) {
                int col = c0 + wn * 32 + nf * 8 + ((lane & 3) << 1);
                float b0 = __ldg(bo + col), b1 = __ldg(bo + col + 1);
                float2 o0 = {fmaxf(e[mf][nf][0] + b0, 0.f), fmaxf(e[mf][nf][1] + b1, 0.f)};
                float2 o1 = {fmaxf(e[mf][nf][2] + b0, 0.f), fmaxf(e[mf][nf][3] + b1, 0.f)};
                *(float2*)(out + (size_t)(b * 128 + row) * DOUT_ + col)     = o0;
                *(float2*)(out + (size_t)(b * 128 + row + 8) * DOUT_ + col) = o1;
            }
        }
    }
}

// ================================================================================
// Launch
// ================================================================================
extern "C" void kernel_launch(void* const* d_in, const int* in_sizes, int n_in,
                              void* d_out, int out_size)
{
    const float* x    = (const float*)d_in[0];
    const float* mask = (const float*)d_in[1];
    const float* Wv   = (const float*)d_in[2];
    const float* bv   = (const float*)d_in[3];
    const float* Wq   = (const float*)d_in[4];
    const float* bq   = (const float*)d_in[5];
    const float* Wk   = (const float*)d_in[6];
    const float* bk   = (const float*)d_in[7];
    const float* Wo   = (const float*)d_in[8];
    const float* bo   = (const float*)d_in[9];

    float* out     = (float*)d_out;
    float* att_out = out + (size_t)B_ * N_ * DOUT_;

    cudaFuncSetAttribute(qkv_tc,     cudaFuncAttributeMaxDynamicSharedMemorySize, QKV_SMEM);
    cudaFuncSetAttribute(attn_fused, cudaFuncAttributeMaxDynamicSharedMemorySize, ATTN_SMEM);

    split_x_kernel<<<1024, 256>>>(x);
    split_w_kernel<<<12, 256>>>(Wv, Wq, Wk, Wo);
    qkv_tc<<<dim3(10, 1024), 256, QKV_SMEM>>>(bv, bq, bk);
    attn_fused<<<2048, 256, ATTN_SMEM>>>(mask, bo, out, att_out);
}